// round 16
// baseline (speedup 1.0000x reference)
#include <cuda_runtime.h>
#include <math.h>

// SpectralConv2d: B=8, C=64, H=W=256, modes 16x16.
// R15: k1a reverted to unroll 2 (R13 config); k2 split into k2a (grid 2048,
// i-quarter partials, high occupancy) + k2b (reduce + inverse-k DFT).

#define NIMG 512              // B*C images of 256x256

// tables (angle a = 2*pi/256)
__device__ float2 g_tab[256 * 16];   // [t][k] (cos akt, sin akt)
__device__ float  g_tabC[16 * 256];  // [k][t] cos
__device__ float  g_tabS[16 * 256];  // [k][t] sin
// k1 phase-1 folded table: [h][32] for h=0..63
__device__ float  g_tab1[64 * 32];
// A[img][k][x] intermediate (H-DFT result), 16MB
__device__ float2 g_A[(size_t)NIMG * 16 * 256];
// X_ft corner per (b,i): [img][k*16+w], complex
__device__ float2 g_X[NIMG * 256];
// G partials: [bo*4+iq][elem]
__device__ float2 g_Gp[(size_t)NIMG * 4 * 256];
// Z per (b,o): [img][p][j], j<16: cos-coeff, j>=16: sin-coeff
__device__ float  g_Z[(size_t)NIMG * 256 * 32];

// ---------------- table init ------------------------------------------------
__global__ void k_init() {
    int i = blockIdx.x * blockDim.x + threadIdx.x;
    if (i < 4096) {
        int t = i >> 4, k = i & 15;
        int m = (t * k) & 255;
        double s, c;
        sincospi((double)m / 128.0, &s, &c);       // angle = 2*pi*m/256
        g_tab[i] = make_float2((float)c, (float)s);
        g_tabC[k * 256 + t] = (float)c;
        g_tabS[k * 256 + t] = (float)s;
    }
    if (i < 2048) {
        int h = i >> 5, j = i & 31;
        int m = j & 7;
        int k = ((j & 15) < 8) ? (2 * m) : (2 * m + 1);
        int mm = (h * k) & 255;
        double s, c;
        sincospi((double)mm / 128.0, &s, &c);
        g_tab1[i] = (j < 16) ? (float)c : (float)s;
    }
}

// ---------------- K1a: folded partial DFT over H -> g_A ---------------------
__global__ void __launch_bounds__(256, 4) k1a(const float* __restrict__ x) {
    __shared__ __align__(16) float s_t1[64 * 32];   // 8KB
    int img = blockIdx.x, tid = threadIdx.x;

    for (int i = tid; i < 2048; i += 256) s_t1[i] = g_tab1[i];
    __syncthreads();

    const float* xp = x + (size_t)img * 65536 + tid;
    float x0   = xp[0];
    float x64v = xp[64 * 256];
    float x128 = xp[128 * 256];
    float x192 = xp[192 * 256];

    float arE[8], arO[8], asE[8], asO[8];
#pragma unroll
    for (int m = 0; m < 8; m++) { arE[m] = 0.f; arO[m] = 0.f; asE[m] = 0.f; asO[m] = 0.f; }

#pragma unroll 2
    for (int h = 1; h < 64; h++) {
        float a1 = xp[(size_t)h * 256];
        float a2 = xp[(size_t)(256 - h) * 256];
        float a3 = xp[(size_t)(128 - h) * 256];
        float a4 = xp[(size_t)(128 + h) * 256];
        float u1 = a1 + a2, v1 = a1 - a2;
        float u2 = a3 + a4, v2 = a3 - a4;
        float uE = u1 + u2, uO = u1 - u2;
        float vE = v1 - v2, vO = v1 + v2;
        const float4* t4 = (const float4*)(s_t1 + h * 32);   // broadcast LDS.128
        float4 cE0 = t4[0], cE1 = t4[1], cO0 = t4[2], cO1 = t4[3];
        float4 sE0 = t4[4], sE1 = t4[5], sO0 = t4[6], sO1 = t4[7];
        arE[0] = fmaf(uE, cE0.x, arE[0]); arE[1] = fmaf(uE, cE0.y, arE[1]);
        arE[2] = fmaf(uE, cE0.z, arE[2]); arE[3] = fmaf(uE, cE0.w, arE[3]);
        arE[4] = fmaf(uE, cE1.x, arE[4]); arE[5] = fmaf(uE, cE1.y, arE[5]);
        arE[6] = fmaf(uE, cE1.z, arE[6]); arE[7] = fmaf(uE, cE1.w, arE[7]);
        arO[0] = fmaf(uO, cO0.x, arO[0]); arO[1] = fmaf(uO, cO0.y, arO[1]);
        arO[2] = fmaf(uO, cO0.z, arO[2]); arO[3] = fmaf(uO, cO0.w, arO[3]);
        arO[4] = fmaf(uO, cO1.x, arO[4]); arO[5] = fmaf(uO, cO1.y, arO[5]);
        arO[6] = fmaf(uO, cO1.z, arO[6]); arO[7] = fmaf(uO, cO1.w, arO[7]);
        asE[0] = fmaf(vE, sE0.x, asE[0]); asE[1] = fmaf(vE, sE0.y, asE[1]);
        asE[2] = fmaf(vE, sE0.z, asE[2]); asE[3] = fmaf(vE, sE0.w, asE[3]);
        asE[4] = fmaf(vE, sE1.x, asE[4]); asE[5] = fmaf(vE, sE1.y, asE[5]);
        asE[6] = fmaf(vE, sE1.z, asE[6]); asE[7] = fmaf(vE, sE1.w, asE[7]);
        asO[0] = fmaf(vO, sO0.x, asO[0]); asO[1] = fmaf(vO, sO0.y, asO[1]);
        asO[2] = fmaf(vO, sO0.z, asO[2]); asO[3] = fmaf(vO, sO0.w, asO[3]);
        asO[4] = fmaf(vO, sO1.x, asO[4]); asO[5] = fmaf(vO, sO1.y, asO[5]);
        asO[6] = fmaf(vO, sO1.z, asO[6]); asO[7] = fmaf(vO, sO1.w, asO[7]);
    }

    float u64v = x64v + x192, v64v = x64v - x192;
    float2* ap = g_A + (size_t)img * 4096 + tid;
    float sgn = 1.f;
#pragma unroll
    for (int m = 0; m < 8; m++) {
        ap[(2 * m) * 256]     = make_float2(x0 + x128 + arE[m] + sgn * u64v, asE[m]);
        ap[(2 * m + 1) * 256] = make_float2(x0 - x128 + arO[m], asO[m] + sgn * v64v);
        sgn = -sgn;
    }
}

// ---------------- K1b: corner DFT over W: A -> X ----------------------------
__global__ void __launch_bounds__(256) k1b() {
    extern __shared__ __align__(16) char smem_raw[];
    float2* s_A   = (float2*)smem_raw;             // [k][x] 32KB
    float2* s_tab = (float2*)(smem_raw + 32768);   // [t][16] 32KB
    int img = blockIdx.x, tid = threadIdx.x;

    {
        const float4* asrc = (const float4*)(g_A + (size_t)img * 4096);
        float4* adst = (float4*)s_A;
#pragma unroll
        for (int it = 0; it < 8; it++) adst[tid + it * 256] = asrc[tid + it * 256];
    }
    for (int i = tid; i < 4096; i += 256) s_tab[i] = g_tab[i];
    __syncthreads();

    int k = tid >> 4, w = tid & 15;
    float xr = 0.f, xi = 0.f;
#pragma unroll 4
    for (int xx = 0; xx < 256; xx++) {
        float2 a  = s_A[k * 256 + xx];     // broadcast
        float2 cs = s_tab[xx * 16 + w];
        xr += a.x * cs.x - a.y * cs.y;
        xi -= a.y * cs.x + a.x * cs.y;
    }
    g_X[img * 256 + tid] = make_float2(xr, xi);
}

// ---------------- K2a: channel-mix partials (grid = NIMG*4) -----------------
// Block = (b, o, iq). 16 i's per block; thread=(ig, e4); fully unrolled ->
// 16 LDG.128 in flight per thread. Partial G to global.
__global__ void __launch_bounds__(256) k2a(const float* __restrict__ wre,
                                           const float* __restrict__ wim) {
    __shared__ float2 sPart[4][256];
    int bo = blockIdx.x >> 2, iq = blockIdx.x & 3;
    int b = bo >> 6, o = bo & 63;
    int tid = threadIdx.x, ig = tid >> 6, e4 = tid & 63;

    const float4* wre4 = (const float4*)wre;
    const float4* wim4 = (const float4*)wim;
    const float4* X4 = (const float4*)(g_X + (size_t)b * 64 * 256);

    float gr[4] = {0.f, 0.f, 0.f, 0.f};
    float gi[4] = {0.f, 0.f, 0.f, 0.f};
#pragma unroll
    for (int step = 0; step < 4; step++) {
        int i = iq * 16 + step * 4 + ig;
        size_t wrow = (size_t)(i * 64 + o) * 64 + e4;   // float4 index
        float4 wr4 = wre4[wrow];
        float4 wi4 = wim4[wrow];
        float4 x01 = X4[i * 128 + 2 * e4];
        float4 x23 = X4[i * 128 + 2 * e4 + 1];
        gr[0] = fmaf(x01.x, wr4.x, fmaf(-x01.y, wi4.x, gr[0]));
        gi[0] = fmaf(x01.x, wi4.x, fmaf( x01.y, wr4.x, gi[0]));
        gr[1] = fmaf(x01.z, wr4.y, fmaf(-x01.w, wi4.y, gr[1]));
        gi[1] = fmaf(x01.z, wi4.y, fmaf( x01.w, wr4.y, gi[1]));
        gr[2] = fmaf(x23.x, wr4.z, fmaf(-x23.y, wi4.z, gr[2]));
        gi[2] = fmaf(x23.x, wi4.z, fmaf( x23.y, wr4.z, gi[2]));
        gr[3] = fmaf(x23.z, wr4.w, fmaf(-x23.w, wi4.w, gr[3]));
        gi[3] = fmaf(x23.z, wi4.w, fmaf( x23.w, wr4.w, gi[3]));
    }
#pragma unroll
    for (int j = 0; j < 4; j++)
        sPart[ig][4 * e4 + j] = make_float2(gr[j], gi[j]);
    __syncthreads();

    float2 p0 = sPart[0][tid], p1 = sPart[1][tid];
    float2 p2 = sPart[2][tid], p3 = sPart[3][tid];
    g_Gp[(size_t)blockIdx.x * 256 + tid] =
        make_float2((p0.x + p1.x) + (p2.x + p3.x),
                    (p0.y + p1.y) + (p2.y + p3.y));
}

// ---------------- K2b: reduce partials + inverse-k DFT -> Z -----------------
__global__ void __launch_bounds__(256) k2b() {
    __shared__ float2 sG[256];
    int bo = blockIdx.x, tid = threadIdx.x;
    {
        const float2* gp = g_Gp + (size_t)bo * 4 * 256 + tid;
        float2 p0 = gp[0], p1 = gp[256], p2 = gp[512], p3 = gp[768];
        sG[tid] = make_float2((p0.x + p1.x) + (p2.x + p3.x),
                              (p0.y + p1.y) + (p2.y + p3.y));
    }
    __syncthreads();

    int p = tid;
    float2 tp[16];
#pragma unroll
    for (int k = 0; k < 16; k++)
        tp[k] = make_float2(g_tabC[k * 256 + p], g_tabS[k * 256 + p]);

    float zc[16], zs[16];
#pragma unroll
    for (int w = 0; w < 16; w++) {
        float yr = 0.f, yi = 0.f;
#pragma unroll
        for (int k = 0; k < 16; k++) {
            float2 g = sG[k * 16 + w];
            yr += g.x * tp[k].x - g.y * tp[k].y;
            yi += g.x * tp[k].y + g.y * tp[k].x;
        }
        zc[w] = yr; zs[w] = -yi;
    }
    const float s1 = 1.0f / 65536.0f, s2 = 2.0f / 65536.0f;
    zc[0] *= s1; zs[0] = 0.f;
#pragma unroll
    for (int w = 1; w < 16; w++) { zc[w] *= s2; zs[w] *= s2; }

    float4* z4 = (float4*)(g_Z + ((size_t)bo * 256 + p) * 32);
    z4[0] = make_float4(zc[0],  zc[1],  zc[2],  zc[3]);
    z4[1] = make_float4(zc[4],  zc[5],  zc[6],  zc[7]);
    z4[2] = make_float4(zc[8],  zc[9],  zc[10], zc[11]);
    z4[3] = make_float4(zc[12], zc[13], zc[14], zc[15]);
    z4[4] = make_float4(zs[0],  zs[1],  zs[2],  zs[3]);
    z4[5] = make_float4(zs[4],  zs[5],  zs[6],  zs[7]);
    z4[6] = make_float4(zs[8],  zs[9],  zs[10], zs[11]);
    z4[7] = make_float4(zs[12], zs[13], zs[14], zs[15]);
}

// ---------------- K3: folded inverse W transform (R11 version) --------------
#define ZS 36
__global__ void __launch_bounds__(256) k3(float* __restrict__ out) {
    __shared__ __align__(16) float s_z[64 * ZS];     // 9KB z tile (padded)
    __shared__ float s_bc[16 * 65];                  // basis cos [w][qs]
    __shared__ float s_bs[16 * 65];                  // basis sin [w][qs]
    int img = blockIdx.x >> 2, tile = blockIdx.x & 3, tid = threadIdx.x;

    {
        const float4* zsrc = (const float4*)(g_Z + (size_t)img * 8192 + tile * 2048);
        float4* zdst = (float4*)s_z;
#pragma unroll
        for (int it = 0; it < 2; it++) {
            int i = tid + it * 256;
            int row = i >> 3, t = i & 7;
            zdst[row * (ZS / 4) + t] = zsrc[i];
        }
    }
    for (int i = tid; i < 1024; i += 256) {
        int t = i >> 4, k = i & 15;
        float2 cs = g_tab[i];
        s_bc[k * 65 + t] = cs.x;
        s_bs[k * 65 + t] = cs.y;
    }
    __syncthreads();

    int qs = tid & 63, pg = tid >> 6;
    float* ob = out + (size_t)img * 65536 + (size_t)tile * 64 * 256;

    if (qs != 0) {
        float c[16], s[16];
#pragma unroll
        for (int w = 0; w < 16; w++) {
            c[w] = s_bc[w * 65 + qs];
            s[w] = s_bs[w * 65 + qs];
        }
        for (int pi = 0; pi < 16; pi++) {
            int p = pg * 16 + pi;
            const float4* z4 = (const float4*)(s_z + p * ZS);
            float z[32];
#pragma unroll
            for (int t = 0; t < 8; t++) {
                float4 v = z4[t];
                z[4 * t] = v.x; z[4 * t + 1] = v.y; z[4 * t + 2] = v.z; z[4 * t + 3] = v.w;
            }
            float Ce = 0.f, Co = 0.f, Se = 0.f, So = 0.f;
#pragma unroll
            for (int m = 0; m < 8; m++) {
                Ce = fmaf(z[2 * m],          c[2 * m],     Ce);
                Co = fmaf(z[2 * m + 1],      c[2 * m + 1], Co);
                Se = fmaf(z[16 + 2 * m],     s[2 * m],     Se);
                So = fmaf(z[16 + 2 * m + 1], s[2 * m + 1], So);
            }
            float t1 = Ce + Co, t2 = Se + So;
            float t3 = Ce - Co, t4 = So - Se;
            float* op = ob + (size_t)p * 256;
            op[qs]        = t1 + t2;
            op[256 - qs]  = t1 - t2;
            op[128 - qs]  = t3 + t4;
            op[128 + qs]  = t3 - t4;
        }
    }

    if (tid < 64) {
        int p = tid;
        const float4* z4 = (const float4*)(s_z + p * ZS);
        float z[32];
#pragma unroll
        for (int t = 0; t < 8; t++) {
            float4 v = z4[t];
            z[4 * t] = v.x; z[4 * t + 1] = v.y; z[4 * t + 2] = v.z; z[4 * t + 3] = v.w;
        }
        float o0 = 0.f, o128 = 0.f, c64 = 0.f, s64 = 0.f;
#pragma unroll
        for (int w = 0; w < 16; w++) {
            o0 += z[w];
            o128 += (w & 1) ? -z[w] : z[w];
        }
#pragma unroll
        for (int m = 0; m < 4; m++) {
            c64 += z[4 * m]          - z[4 * m + 2];
            s64 += z[16 + 4 * m + 1] - z[16 + 4 * m + 3];
        }
        float* op = ob + (size_t)p * 256;
        op[0]   = o0;
        op[128] = o128;
        op[64]  = c64 + s64;
        op[192] = c64 - s64;
    }
}

extern "C" void kernel_launch(void* const* d_in, const int* in_sizes, int n_in,
                              void* d_out, int out_size) {
    const float* x   = (const float*)d_in[0];
    const float* wre = (const float*)d_in[1];
    const float* wim = (const float*)d_in[2];
    float* out = (float*)d_out;

    cudaFuncSetAttribute(k1b, cudaFuncAttributeMaxDynamicSharedMemorySize, 65536);

    k_init<<<16, 256>>>();
    k1a<<<NIMG, 256>>>(x);
    k1b<<<NIMG, 256, 65536>>>();
    k2a<<<NIMG * 4, 256>>>(wre, wim);
    k2b<<<NIMG, 256>>>();
    k3 <<<NIMG * 4, 256>>>(out);
}

// round 17
// speedup vs baseline: 1.1193x; 1.1193x over previous
#include <cuda_runtime.h>
#include <math.h>

// SpectralConv2d: B=8, C=64, H=W=256, modes 16x16.
// R16: g_Z + k2b deleted; inverse-k DFT (phase B) fused into k3 from G
// partials. fp32 table init. Pipeline: init, k1a, k1b, k2a, k3.

#define NIMG 512              // B*C images of 256x256

// tables (angle a = 2*pi/256)
__device__ float2 g_tab[256 * 16];   // [t][k] (cos akt, sin akt)
__device__ float  g_tabC[16 * 256];  // [k][t] cos
__device__ float  g_tabS[16 * 256];  // [k][t] sin
// k1 phase-1 folded table: [h][32] for h=0..63
__device__ float  g_tab1[64 * 32];
// A[img][k][x] intermediate (H-DFT result), 16MB
__device__ float2 g_A[(size_t)NIMG * 16 * 256];
// X_ft corner per (b,i): [img][k*16+w], complex
__device__ float2 g_X[NIMG * 256];
// G partials: [bo*4+iq][elem]
__device__ float2 g_Gp[(size_t)NIMG * 4 * 256];

// ---------------- table init (fp32 sincospi) ---------------------------------
__global__ void k_init() {
    int i = blockIdx.x * blockDim.x + threadIdx.x;
    if (i < 4096) {
        int t = i >> 4, k = i & 15;
        int m = (t * k) & 255;
        float s, c;
        sincospif((float)m / 128.0f, &s, &c);      // angle = 2*pi*m/256
        g_tab[i] = make_float2(c, s);
        g_tabC[k * 256 + t] = c;
        g_tabS[k * 256 + t] = s;
    }
    if (i < 2048) {
        int h = i >> 5, j = i & 31;
        int m = j & 7;
        int k = ((j & 15) < 8) ? (2 * m) : (2 * m + 1);
        int mm = (h * k) & 255;
        float s, c;
        sincospif((float)mm / 128.0f, &s, &c);
        g_tab1[i] = (j < 16) ? c : s;
    }
}

// ---------------- K1a: folded partial DFT over H -> g_A ---------------------
__global__ void __launch_bounds__(256, 4) k1a(const float* __restrict__ x) {
    __shared__ __align__(16) float s_t1[64 * 32];   // 8KB
    int img = blockIdx.x, tid = threadIdx.x;

    for (int i = tid; i < 2048; i += 256) s_t1[i] = g_tab1[i];
    __syncthreads();

    const float* xp = x + (size_t)img * 65536 + tid;
    float x0   = xp[0];
    float x64v = xp[64 * 256];
    float x128 = xp[128 * 256];
    float x192 = xp[192 * 256];

    float arE[8], arO[8], asE[8], asO[8];
#pragma unroll
    for (int m = 0; m < 8; m++) { arE[m] = 0.f; arO[m] = 0.f; asE[m] = 0.f; asO[m] = 0.f; }

#pragma unroll 2
    for (int h = 1; h < 64; h++) {
        float a1 = xp[(size_t)h * 256];
        float a2 = xp[(size_t)(256 - h) * 256];
        float a3 = xp[(size_t)(128 - h) * 256];
        float a4 = xp[(size_t)(128 + h) * 256];
        float u1 = a1 + a2, v1 = a1 - a2;
        float u2 = a3 + a4, v2 = a3 - a4;
        float uE = u1 + u2, uO = u1 - u2;
        float vE = v1 - v2, vO = v1 + v2;
        const float4* t4 = (const float4*)(s_t1 + h * 32);   // broadcast LDS.128
        float4 cE0 = t4[0], cE1 = t4[1], cO0 = t4[2], cO1 = t4[3];
        float4 sE0 = t4[4], sE1 = t4[5], sO0 = t4[6], sO1 = t4[7];
        arE[0] = fmaf(uE, cE0.x, arE[0]); arE[1] = fmaf(uE, cE0.y, arE[1]);
        arE[2] = fmaf(uE, cE0.z, arE[2]); arE[3] = fmaf(uE, cE0.w, arE[3]);
        arE[4] = fmaf(uE, cE1.x, arE[4]); arE[5] = fmaf(uE, cE1.y, arE[5]);
        arE[6] = fmaf(uE, cE1.z, arE[6]); arE[7] = fmaf(uE, cE1.w, arE[7]);
        arO[0] = fmaf(uO, cO0.x, arO[0]); arO[1] = fmaf(uO, cO0.y, arO[1]);
        arO[2] = fmaf(uO, cO0.z, arO[2]); arO[3] = fmaf(uO, cO0.w, arO[3]);
        arO[4] = fmaf(uO, cO1.x, arO[4]); arO[5] = fmaf(uO, cO1.y, arO[5]);
        arO[6] = fmaf(uO, cO1.z, arO[6]); arO[7] = fmaf(uO, cO1.w, arO[7]);
        asE[0] = fmaf(vE, sE0.x, asE[0]); asE[1] = fmaf(vE, sE0.y, asE[1]);
        asE[2] = fmaf(vE, sE0.z, asE[2]); asE[3] = fmaf(vE, sE0.w, asE[3]);
        asE[4] = fmaf(vE, sE1.x, asE[4]); asE[5] = fmaf(vE, sE1.y, asE[5]);
        asE[6] = fmaf(vE, sE1.z, asE[6]); asE[7] = fmaf(vE, sE1.w, asE[7]);
        asO[0] = fmaf(vO, sO0.x, asO[0]); asO[1] = fmaf(vO, sO0.y, asO[1]);
        asO[2] = fmaf(vO, sO0.z, asO[2]); asO[3] = fmaf(vO, sO0.w, asO[3]);
        asO[4] = fmaf(vO, sO1.x, asO[4]); asO[5] = fmaf(vO, sO1.y, asO[5]);
        asO[6] = fmaf(vO, sO1.z, asO[6]); asO[7] = fmaf(vO, sO1.w, asO[7]);
    }

    float u64v = x64v + x192, v64v = x64v - x192;
    float2* ap = g_A + (size_t)img * 4096 + tid;
    float sgn = 1.f;
#pragma unroll
    for (int m = 0; m < 8; m++) {
        ap[(2 * m) * 256]     = make_float2(x0 + x128 + arE[m] + sgn * u64v, asE[m]);
        ap[(2 * m + 1) * 256] = make_float2(x0 - x128 + arO[m], asO[m] + sgn * v64v);
        sgn = -sgn;
    }
}

// ---------------- K1b: corner DFT over W: A -> X ----------------------------
__global__ void __launch_bounds__(256) k1b() {
    extern __shared__ __align__(16) char smem_raw[];
    float2* s_A   = (float2*)smem_raw;             // [k][x] 32KB
    float2* s_tab = (float2*)(smem_raw + 32768);   // [t][16] 32KB
    int img = blockIdx.x, tid = threadIdx.x;

    {
        const float4* asrc = (const float4*)(g_A + (size_t)img * 4096);
        float4* adst = (float4*)s_A;
#pragma unroll
        for (int it = 0; it < 8; it++) adst[tid + it * 256] = asrc[tid + it * 256];
    }
    for (int i = tid; i < 4096; i += 256) s_tab[i] = g_tab[i];
    __syncthreads();

    int k = tid >> 4, w = tid & 15;
    float xr = 0.f, xi = 0.f;
#pragma unroll 4
    for (int xx = 0; xx < 256; xx++) {
        float2 a  = s_A[k * 256 + xx];     // broadcast
        float2 cs = s_tab[xx * 16 + w];
        xr += a.x * cs.x - a.y * cs.y;
        xi -= a.y * cs.x + a.x * cs.y;
    }
    g_X[img * 256 + tid] = make_float2(xr, xi);
}

// ---------------- K2a: channel-mix partials (grid = NIMG*4) -----------------
__global__ void __launch_bounds__(256) k2a(const float* __restrict__ wre,
                                           const float* __restrict__ wim) {
    __shared__ float2 sPart[4][256];
    int bo = blockIdx.x >> 2, iq = blockIdx.x & 3;
    int b = bo >> 6, o = bo & 63;
    int tid = threadIdx.x, ig = tid >> 6, e4 = tid & 63;

    const float4* wre4 = (const float4*)wre;
    const float4* wim4 = (const float4*)wim;
    const float4* X4 = (const float4*)(g_X + (size_t)b * 64 * 256);

    float gr[4] = {0.f, 0.f, 0.f, 0.f};
    float gi[4] = {0.f, 0.f, 0.f, 0.f};
#pragma unroll
    for (int step = 0; step < 4; step++) {
        int i = iq * 16 + step * 4 + ig;
        size_t wrow = (size_t)(i * 64 + o) * 64 + e4;   // float4 index
        float4 wr4 = wre4[wrow];
        float4 wi4 = wim4[wrow];
        float4 x01 = X4[i * 128 + 2 * e4];
        float4 x23 = X4[i * 128 + 2 * e4 + 1];
        gr[0] = fmaf(x01.x, wr4.x, fmaf(-x01.y, wi4.x, gr[0]));
        gi[0] = fmaf(x01.x, wi4.x, fmaf( x01.y, wr4.x, gi[0]));
        gr[1] = fmaf(x01.z, wr4.y, fmaf(-x01.w, wi4.y, gr[1]));
        gi[1] = fmaf(x01.z, wi4.y, fmaf( x01.w, wr4.y, gi[1]));
        gr[2] = fmaf(x23.x, wr4.z, fmaf(-x23.y, wi4.z, gr[2]));
        gi[2] = fmaf(x23.x, wi4.z, fmaf( x23.y, wr4.z, gi[2]));
        gr[3] = fmaf(x23.z, wr4.w, fmaf(-x23.w, wi4.w, gr[3]));
        gi[3] = fmaf(x23.z, wi4.w, fmaf( x23.w, wr4.w, gi[3]));
    }
#pragma unroll
    for (int j = 0; j < 4; j++)
        sPart[ig][4 * e4 + j] = make_float2(gr[j], gi[j]);
    __syncthreads();

    float2 p0 = sPart[0][tid], p1 = sPart[1][tid];
    float2 p2 = sPart[2][tid], p3 = sPart[3][tid];
    g_Gp[(size_t)blockIdx.x * 256 + tid] =
        make_float2((p0.x + p1.x) + (p2.x + p3.x),
                    (p0.y + p1.y) + (p2.y + p3.y));
}

// ---------------- K3: G -> Z (in smem) -> folded inverse W transform --------
// Grid = NIMG*4; block owns 64 p-rows of one image. Reduces G partials,
// computes its z-tile via inverse-k DFT (phase B), then folded W transform.
#define ZS 36
__global__ void __launch_bounds__(256) k3(float* __restrict__ out) {
    __shared__ __align__(16) float s_z[64 * ZS];     // 9KB z tile (padded)
    __shared__ float s_bc[16 * 65];                  // W-basis cos [w][qs]
    __shared__ float s_bs[16 * 65];                  // W-basis sin [w][qs]
    __shared__ float2 sG[256];                       // G[k*16+w]
    int img = blockIdx.x >> 2, tile = blockIdx.x & 3, tid = threadIdx.x;

    {   // reduce 4 partials -> G
        const float2* gp = g_Gp + (size_t)img * 1024 + tid;
        float2 p0 = gp[0], p1 = gp[256], p2 = gp[512], p3 = gp[768];
        sG[tid] = make_float2((p0.x + p1.x) + (p2.x + p3.x),
                              (p0.y + p1.y) + (p2.y + p3.y));
    }
    for (int i = tid; i < 1024; i += 256) {
        int t = i >> 4, k = i & 15;
        float2 cs = g_tab[i];
        s_bc[k * 65 + t] = cs.x;
        s_bs[k * 65 + t] = cs.y;
    }
    __syncthreads();

    // Phase B: z[pp][w] for this tile's 64 rows. tid -> (pp = tid&63, wg = tid>>6)
    {
        int pp = tid & 63, wg = tid >> 6;
        int p = tile * 64 + pp;
        float2 tp[16];
#pragma unroll
        for (int k = 0; k < 16; k++)
            tp[k] = make_float2(g_tabC[k * 256 + p], g_tabS[k * 256 + p]);  // coalesced

        const float s1 = 1.0f / 65536.0f, s2 = 2.0f / 65536.0f;
#pragma unroll
        for (int wj = 0; wj < 4; wj++) {
            int w = wg * 4 + wj;
            float yr = 0.f, yi = 0.f;
#pragma unroll
            for (int k = 0; k < 16; k++) {
                float2 g = sG[k * 16 + w];          // broadcast per warp
                yr += g.x * tp[k].x - g.y * tp[k].y;
                yi += g.x * tp[k].y + g.y * tp[k].x;
            }
            float zc = yr, zs = -yi;
            if (w == 0) { zc *= s1; zs = 0.f; }
            else        { zc *= s2; zs *= s2; }
            s_z[pp * ZS + w]      = zc;
            s_z[pp * ZS + 16 + w] = zs;
        }
    }
    __syncthreads();

    int qs = tid & 63, pg = tid >> 6;
    float* ob = out + (size_t)img * 65536 + (size_t)tile * 64 * 256;

    if (qs != 0) {
        float c[16], s[16];
#pragma unroll
        for (int w = 0; w < 16; w++) {
            c[w] = s_bc[w * 65 + qs];
            s[w] = s_bs[w * 65 + qs];
        }
        for (int pi = 0; pi < 16; pi++) {
            int p = pg * 16 + pi;
            const float4* z4 = (const float4*)(s_z + p * ZS);
            float z[32];
#pragma unroll
            for (int t = 0; t < 8; t++) {
                float4 v = z4[t];
                z[4 * t] = v.x; z[4 * t + 1] = v.y; z[4 * t + 2] = v.z; z[4 * t + 3] = v.w;
            }
            float Ce = 0.f, Co = 0.f, Se = 0.f, So = 0.f;
#pragma unroll
            for (int m = 0; m < 8; m++) {
                Ce = fmaf(z[2 * m],          c[2 * m],     Ce);
                Co = fmaf(z[2 * m + 1],      c[2 * m + 1], Co);
                Se = fmaf(z[16 + 2 * m],     s[2 * m],     Se);
                So = fmaf(z[16 + 2 * m + 1], s[2 * m + 1], So);
            }
            float t1 = Ce + Co, t2 = Se + So;
            float t3 = Ce - Co, t4 = So - Se;
            float* op = ob + (size_t)p * 256;
            op[qs]        = t1 + t2;
            op[256 - qs]  = t1 - t2;
            op[128 - qs]  = t3 + t4;
            op[128 + qs]  = t3 - t4;
        }
    }

    if (tid < 64) {
        int p = tid;
        const float4* z4 = (const float4*)(s_z + p * ZS);
        float z[32];
#pragma unroll
        for (int t = 0; t < 8; t++) {
            float4 v = z4[t];
            z[4 * t] = v.x; z[4 * t + 1] = v.y; z[4 * t + 2] = v.z; z[4 * t + 3] = v.w;
        }
        float o0 = 0.f, o128 = 0.f, c64 = 0.f, s64 = 0.f;
#pragma unroll
        for (int w = 0; w < 16; w++) {
            o0 += z[w];
            o128 += (w & 1) ? -z[w] : z[w];
        }
#pragma unroll
        for (int m = 0; m < 4; m++) {
            c64 += z[4 * m]          - z[4 * m + 2];
            s64 += z[16 + 4 * m + 1] - z[16 + 4 * m + 3];
        }
        float* op = ob + (size_t)p * 256;
        op[0]   = o0;
        op[128] = o128;
        op[64]  = c64 + s64;
        op[192] = c64 - s64;
    }
}

extern "C" void kernel_launch(void* const* d_in, const int* in_sizes, int n_in,
                              void* d_out, int out_size) {
    const float* x   = (const float*)d_in[0];
    const float* wre = (const float*)d_in[1];
    const float* wim = (const float*)d_in[2];
    float* out = (float*)d_out;

    cudaFuncSetAttribute(k1b, cudaFuncAttributeMaxDynamicSharedMemorySize, 65536);

    k_init<<<16, 256>>>();
    k1a<<<NIMG, 256>>>(x);
    k1b<<<NIMG, 256, 65536>>>();
    k2a<<<NIMG * 4, 256>>>(wre, wim);
    k3 <<<NIMG * 4, 256>>>(out);
}